// round 1
// baseline (speedup 1.0000x reference)
#include <cuda_runtime.h>
#include <cstdint>
#include <math.h>

// Problem constants
#define B_   32
#define D_   512
#define NH_  8
#define DH_  64
#define DEPTH_ 8
#define MLP_ 2048
#define NC_  256
#define S_   512
#define M_   (B_*S_)   // 16384 rows

// ---------------- scratch (device globals; no allocation allowed) -------------
__device__ __align__(256) float g_x[M_*D_];      // residual stream
__device__ __align__(256) float g_y[M_*D_];      // LN out / attention out
__device__ __align__(256) float g_big[M_*MLP_];  // qkv (stride 1536) / mlp hidden

// ---------------- helpers ----------------------------------------------------
__device__ __forceinline__ float f2tf32(float x){
    uint32_t u;
    asm("cvt.rna.tf32.f32 %0, %1;" : "=r"(u) : "f"(x));
    return __uint_as_float(u);
}

__device__ __forceinline__ float blocksum128(float v, volatile float* red){
    #pragma unroll
    for (int o = 16; o > 0; o >>= 1) v += __shfl_xor_sync(0xffffffffu, v, o);
    if ((threadIdx.x & 31) == 0) red[threadIdx.x >> 5] = v;
    __syncthreads();
    float r = red[0] + red[1] + red[2] + red[3];
    __syncthreads();
    return r;
}

// ---------------- embed + first LN -------------------------------------------
__global__ __launch_bounds__(128) void embed_ln_kernel(
    const float* __restrict__ z, const float* __restrict__ slots,
    const float* __restrict__ pe, const float* __restrict__ spe,
    const float* __restrict__ nw, const float* __restrict__ nb,
    float* __restrict__ x)
{
    __shared__ float red[4];
    const int row = blockIdx.x;          // 0..16383
    const int b   = row >> 9;
    const int tkn = row & 511;
    const int t   = threadIdx.x;
    const int d0  = t * 4;

    float v0, v1, v2, v3;
    if (tkn < NC_) {
        const float4 s4 = *(const float4*)(slots + ((size_t)b*NC_ + tkn)*D_ + d0);
        const float4 p4 = *(const float4*)(spe + (size_t)tkn*D_ + d0);
        v0 = s4.x + p4.x; v1 = s4.y + p4.y; v2 = s4.z + p4.z; v3 = s4.w + p4.w;
    } else {
        const int p = tkn - NC_;
        const float4 p4 = *(const float4*)(pe + (size_t)p*D_ + d0);
        v0 = z[((size_t)b*D_ + d0 + 0)*256 + p] + p4.x;
        v1 = z[((size_t)b*D_ + d0 + 1)*256 + p] + p4.y;
        v2 = z[((size_t)b*D_ + d0 + 2)*256 + p] + p4.z;
        v3 = z[((size_t)b*D_ + d0 + 3)*256 + p] + p4.w;
    }
    float mean = blocksum128(v0+v1+v2+v3, red) * (1.f/512.f);
    float dx = v0-mean, dy = v1-mean, dz = v2-mean, dw = v3-mean;
    float var = blocksum128(dx*dx+dy*dy+dz*dz+dw*dw, red) * (1.f/512.f);
    float rs = rsqrtf(var + 1e-5f);
    const float4 wv = *(const float4*)(nw + d0);
    const float4 bv = *(const float4*)(nb + d0);
    float4 o;
    o.x = dx*rs*wv.x + bv.x;
    o.y = dy*rs*wv.y + bv.y;
    o.z = dz*rs*wv.z + bv.z;
    o.w = dw*rs*wv.w + bv.w;
    *(float4*)(x + (size_t)row*D_ + d0) = o;
}

// ---------------- layernorm ---------------------------------------------------
__global__ __launch_bounds__(128) void ln_kernel(
    const float* __restrict__ xin, const float* __restrict__ w,
    const float* __restrict__ bia, float* __restrict__ yout)
{
    __shared__ float red[4];
    const size_t row = blockIdx.x;
    const int t = threadIdx.x;
    const int d0 = t * 4;
    float4 v = *(const float4*)(xin + row*D_ + d0);
    float mean = blocksum128(v.x+v.y+v.z+v.w, red) * (1.f/512.f);
    float dx = v.x-mean, dy = v.y-mean, dz = v.z-mean, dw = v.w-mean;
    float var = blocksum128(dx*dx+dy*dy+dz*dz+dw*dw, red) * (1.f/512.f);
    float rs = rsqrtf(var + 1e-5f);
    const float4 wv = *(const float4*)(w + d0);
    const float4 bv = *(const float4*)(bia + d0);
    float4 o;
    o.x = dx*rs*wv.x + bv.x;
    o.y = dy*rs*wv.y + bv.y;
    o.z = dz*rs*wv.z + bv.z;
    o.w = dw*rs*wv.w + bv.w;
    *(float4*)(yout + row*D_ + d0) = o;
}

// ---------------- tf32 tensor-core GEMM --------------------------------------
// C[M,N] = A[M,K] @ B[K,N]  (all row-major), 128x128 tile, BK=16, 256 threads.
// EPI: 0 = store, 1 = C += acc + bias (residual), 2 = C = gelu(acc + bias)
template<int EPI>
__global__ __launch_bounds__(256) void gemm_tf32(
    const float* __restrict__ A, const float* __restrict__ Bw,
    const float* __restrict__ bias, float* __restrict__ C,
    int M, int N, int K)
{
    const int bm = blockIdx.y * 128;
    const int bn = blockIdx.x * 128;
    const int tid = threadIdx.x;
    const int warp = tid >> 5, lane = tid & 31;
    const int g = lane >> 2, tg = lane & 3;
    const int wm = (warp & 1) << 6;   // 64-row warp tile
    const int wn = (warp >> 1) << 5;  // 32-col warp tile

    __shared__ float As[2][128*20];   // stride 20 (conflict-free frag loads)
    __shared__ float Bs[2][16*136];   // stride 136

    float c[4][4][4];
    #pragma unroll
    for (int i=0;i<4;i++)
        #pragma unroll
        for (int j=0;j<4;j++)
            #pragma unroll
            for (int r=0;r<4;r++) c[i][j][r] = 0.f;

    const int ar0 = tid >> 2,  ar1 = (tid+256) >> 2;
    const int acl = (tid & 3) * 4;
    const int br0 = tid >> 5,  br1 = (tid >> 5) + 8;
    const int bcl = (tid & 31) * 4;

    float4 ra0, ra1, rb0, rb1;

    auto ldg = [&](int kt){
        ra0 = *(const float4*)(A + (size_t)(bm+ar0)*K + kt*16 + acl);
        ra1 = *(const float4*)(A + (size_t)(bm+ar1)*K + kt*16 + acl);
        rb0 = *(const float4*)(Bw + (size_t)(kt*16+br0)*N + bn + bcl);
        rb1 = *(const float4*)(Bw + (size_t)(kt*16+br1)*N + bn + bcl);
    };
    auto cvt4 = [](float4 v){
        v.x = f2tf32(v.x); v.y = f2tf32(v.y); v.z = f2tf32(v.z); v.w = f2tf32(v.w);
        return v;
    };
    auto sts = [&](int bu){
        *(float4*)(&As[bu][ar0*20 + acl]) = cvt4(ra0);
        *(float4*)(&As[bu][ar1*20 + acl]) = cvt4(ra1);
        *(float4*)(&Bs[bu][br0*136 + bcl]) = cvt4(rb0);
        *(float4*)(&Bs[bu][br1*136 + bcl]) = cvt4(rb1);
    };
    auto compute = [&](int bu){
        #pragma unroll
        for (int ks=0; ks<2; ks++){
            const int kb = ks*8;
            uint32_t af[4][4], bf[4][2];
            #pragma unroll
            for (int mf=0; mf<4; mf++){
                int r0 = wm + mf*16 + g;
                af[mf][0] = __float_as_uint(As[bu][ r0   *20 + kb + tg    ]);
                af[mf][1] = __float_as_uint(As[bu][(r0+8)*20 + kb + tg    ]);
                af[mf][2] = __float_as_uint(As[bu][ r0   *20 + kb + tg + 4]);
                af[mf][3] = __float_as_uint(As[bu][(r0+8)*20 + kb + tg + 4]);
            }
            #pragma unroll
            for (int nf=0; nf<4; nf++){
                int cn = wn + nf*8 + g;
                bf[nf][0] = __float_as_uint(Bs[bu][(kb+tg  )*136 + cn]);
                bf[nf][1] = __float_as_uint(Bs[bu][(kb+tg+4)*136 + cn]);
            }
            #pragma unroll
            for (int mf=0; mf<4; mf++)
                #pragma unroll
                for (int nf=0; nf<4; nf++){
                    asm volatile(
                        "mma.sync.aligned.m16n8k8.row.col.f32.tf32.tf32.f32 "
                        "{%0,%1,%2,%3}, {%4,%5,%6,%7}, {%8,%9}, {%0,%1,%2,%3};"
                        : "+f"(c[mf][nf][0]), "+f"(c[mf][nf][1]),
                          "+f"(c[mf][nf][2]), "+f"(c[mf][nf][3])
                        : "r"(af[mf][0]), "r"(af[mf][1]), "r"(af[mf][2]), "r"(af[mf][3]),
                          "r"(bf[nf][0]), "r"(bf[nf][1]));
                }
        }
    };

    const int KT = K >> 4;
    ldg(0); sts(0);
    __syncthreads();
    int bu = 0;
    for (int kt = 0; kt < KT; kt++){
        const bool more = (kt+1 < KT);
        if (more) ldg(kt+1);
        compute(bu);
        if (more) sts(bu^1);
        __syncthreads();
        bu ^= 1;
    }

    // epilogue
    #pragma unroll
    for (int mf=0; mf<4; mf++){
        #pragma unroll
        for (int nf=0; nf<4; nf++){
            const int row = bm + wm + mf*16 + g;
            const int col = bn + wn + nf*8 + tg*2;
            #pragma unroll
            for (int half=0; half<2; half++){
                const int r = row + half*8;
                float v0 = c[mf][nf][half*2+0];
                float v1 = c[mf][nf][half*2+1];
                float* p = C + (size_t)r*N + col;
                if (EPI == 0){
                    p[0] = v0; p[1] = v1;
                } else if (EPI == 1){
                    p[0] += v0 + bias[col];
                    p[1] += v1 + bias[col+1];
                } else {
                    float t0 = v0 + bias[col];
                    float t1 = v1 + bias[col+1];
                    p[0] = 0.5f*t0*(1.f + erff(t0*0.70710678118654752f));
                    p[1] = 0.5f*t1*(1.f + erff(t1*0.70710678118654752f));
                }
            }
        }
    }
}

// ---------------- causal flash attention (fp32) ------------------------------
// grid (S/64, NH, B), 64 threads, 1 thread = 1 query; K/V tiles in shared.
__global__ __launch_bounds__(64) void attn_kernel(
    const float* __restrict__ qkv, float* __restrict__ o)
{
    const int qt = blockIdx.x;
    const int h  = blockIdx.y;
    const int b  = blockIdx.z;
    const int t  = threadIdx.x;
    const int qi = qt*64 + t;
    const size_t base = (size_t)b * S_ * 1536;

    __shared__ float Ks[64*64];
    __shared__ float Vs[64*64];

    float q[64], acc[64];
    {
        const float* qrow = qkv + base + (size_t)qi*1536 + h*64;
        #pragma unroll
        for (int i=0;i<16;i++){
            float4 v = *(const float4*)(qrow + 4*i);
            q[4*i+0] = v.x*0.125f; q[4*i+1] = v.y*0.125f;
            q[4*i+2] = v.z*0.125f; q[4*i+3] = v.w*0.125f;
        }
    }
    #pragma unroll
    for (int d=0; d<64; d++) acc[d] = 0.f;
    float m = -1e30f, l = 0.f;

    for (int jt = 0; jt <= qt; jt++){
        const int j0 = jt*64;
        __syncthreads();
        for (int j = 0; j < 64; j++){
            Ks[j*64 + t] = qkv[base + (size_t)(j0+j)*1536 +  512 + h*64 + t];
            Vs[j*64 + t] = qkv[base + (size_t)(j0+j)*1536 + 1024 + h*64 + t];
        }
        __syncthreads();
        const int jmax = (jt == qt) ? (t + 1) : 64;
        for (int j = 0; j < jmax; j++){
            float s = 0.f;
            const float4* kr = (const float4*)(Ks + j*64);
            #pragma unroll
            for (int i=0;i<16;i++){
                float4 kv = kr[i];
                s += q[4*i]*kv.x + q[4*i+1]*kv.y + q[4*i+2]*kv.z + q[4*i+3]*kv.w;
            }
            if (s > m){
                float corr = __expf(m - s);
                m = s; l *= corr;
                #pragma unroll
                for (int d=0; d<64; d++) acc[d] *= corr;
            }
            float p = __expf(s - m);
            l += p;
            const float4* vr = (const float4*)(Vs + j*64);
            #pragma unroll
            for (int i=0;i<16;i++){
                float4 vv = vr[i];
                acc[4*i+0] += p*vv.x; acc[4*i+1] += p*vv.y;
                acc[4*i+2] += p*vv.z; acc[4*i+3] += p*vv.w;
            }
        }
    }
    const float inv = 1.f / l;
    float4* orow = (float4*)(o + ((size_t)(b*S_ + qi))*D_ + h*64);
    #pragma unroll
    for (int i=0;i<16;i++){
        float4 v;
        v.x = acc[4*i+0]*inv; v.y = acc[4*i+1]*inv;
        v.z = acc[4*i+2]*inv; v.w = acc[4*i+3]*inv;
        orow[i] = v;
    }
}

// ---------------- output slice + transpose -----------------------------------
__global__ __launch_bounds__(256) void out_kernel(
    const float* __restrict__ x, float* __restrict__ out)
{
    const int idx = blockIdx.x * 256 + threadIdx.x;   // b*512*256 + d*256 + p
    const int p = idx & 255;
    const int d = (idx >> 8) & 511;
    const int b = idx >> 17;
    out[idx] = x[((size_t)b*S_ + (NC_ - 1) + p)*D_ + d];
}

// ---------------- launch ------------------------------------------------------
extern "C" void kernel_launch(void* const* d_in, const int* in_sizes, int n_in,
                              void* d_out, int out_size)
{
    const float* z       = (const float*)d_in[0];
    const float* slots   = (const float*)d_in[1];
    const float* pos_emb = (const float*)d_in[2];
    const float* spe     = (const float*)d_in[3];
    const float* norm_w  = (const float*)d_in[4];
    const float* norm_b  = (const float*)d_in[5];
    const float* ln1_w   = (const float*)d_in[6];
    const float* ln1_b   = (const float*)d_in[7];
    const float* qkv_w   = (const float*)d_in[8];
    const float* out_w   = (const float*)d_in[9];
    const float* out_b   = (const float*)d_in[10];
    const float* ln2_w   = (const float*)d_in[11];
    const float* ln2_b   = (const float*)d_in[12];
    const float* mlp_w1  = (const float*)d_in[13];
    const float* mlp_b1  = (const float*)d_in[14];
    const float* mlp_w2  = (const float*)d_in[15];
    const float* mlp_b2  = (const float*)d_in[16];

    float *x, *y, *big;
    cudaGetSymbolAddress((void**)&x,   g_x);
    cudaGetSymbolAddress((void**)&y,   g_y);
    cudaGetSymbolAddress((void**)&big, g_big);

    embed_ln_kernel<<<M_, 128>>>(z, slots, pos_emb, spe, norm_w, norm_b, x);

    for (int i = 0; i < DEPTH_; i++){
        ln_kernel<<<M_, 128>>>(x, ln1_w + i*D_, ln1_b + i*D_, y);
        gemm_tf32<0><<<dim3(1536/128, M_/128), 256>>>(
            y, qkv_w + (size_t)i*D_*1536, nullptr, big, M_, 1536, D_);
        attn_kernel<<<dim3(S_/64, NH_, B_), 64>>>(big, y);
        gemm_tf32<1><<<dim3(D_/128, M_/128), 256>>>(
            y, out_w + (size_t)i*D_*D_, out_b + i*D_, x, M_, D_, D_);
        ln_kernel<<<M_, 128>>>(x, ln2_w + i*D_, ln2_b + i*D_, y);
        gemm_tf32<2><<<dim3(MLP_/128, M_/128), 256>>>(
            y, mlp_w1 + (size_t)i*D_*MLP_, mlp_b1 + i*MLP_, big, M_, MLP_, D_);
        gemm_tf32<1><<<dim3(D_/128, M_/128), 256>>>(
            big, mlp_w2 + (size_t)i*MLP_*D_, mlp_b2 + i*D_, x, M_, D_, MLP_);
    }

    out_kernel<<<(B_*D_*256)/256, 256>>>(x, (float*)d_out);
}

// round 2
// speedup vs baseline: 1.4566x; 1.4566x over previous
#include <cuda_runtime.h>
#include <cstdint>
#include <math.h>

// Problem constants
#define B_   32
#define D_   512
#define NH_  8
#define DH_  64
#define DEPTH_ 8
#define MLP_ 2048
#define NC_  256
#define S_   512
#define M_   (B_*S_)   // 16384 rows

// ---------------- scratch (device globals; no allocation allowed) -------------
__device__ __align__(256) float g_x[M_*D_];      // residual stream
__device__ __align__(256) float g_y[M_*D_];      // LN out / attention out
__device__ __align__(256) float g_big[M_*MLP_];  // qkv (stride 1536) / mlp hidden

// ---------------- helpers ----------------------------------------------------
__device__ __forceinline__ float f2tf32(float x){
    uint32_t u;
    asm("cvt.rna.tf32.f32 %0, %1;" : "=r"(u) : "f"(x));
    return __uint_as_float(u);
}

__device__ __forceinline__ void mma_tf32(float* c, const uint32_t* a,
                                         uint32_t b0, uint32_t b1){
    asm volatile(
        "mma.sync.aligned.m16n8k8.row.col.f32.tf32.tf32.f32 "
        "{%0,%1,%2,%3}, {%4,%5,%6,%7}, {%8,%9}, {%0,%1,%2,%3};"
        : "+f"(c[0]), "+f"(c[1]), "+f"(c[2]), "+f"(c[3])
        : "r"(a[0]), "r"(a[1]), "r"(a[2]), "r"(a[3]), "r"(b0), "r"(b1));
}

__device__ __forceinline__ void cp16(void* s, const void* g){
    uint32_t sa = (uint32_t)__cvta_generic_to_shared(s);
    asm volatile("cp.async.cg.shared.global [%0], [%1], 16;\n" :: "r"(sa), "l"(g));
}

__device__ __forceinline__ float blocksum128(float v, volatile float* red){
    #pragma unroll
    for (int o = 16; o > 0; o >>= 1) v += __shfl_xor_sync(0xffffffffu, v, o);
    if ((threadIdx.x & 31) == 0) red[threadIdx.x >> 5] = v;
    __syncthreads();
    float r = red[0] + red[1] + red[2] + red[3];
    __syncthreads();
    return r;
}

// ---------------- embed + first LN -------------------------------------------
__global__ __launch_bounds__(128) void embed_ln_kernel(
    const float* __restrict__ z, const float* __restrict__ slots,
    const float* __restrict__ pe, const float* __restrict__ spe,
    const float* __restrict__ nw, const float* __restrict__ nb,
    float* __restrict__ x)
{
    __shared__ float red[4];
    const int row = blockIdx.x;
    const int b   = row >> 9;
    const int tkn = row & 511;
    const int t   = threadIdx.x;
    const int d0  = t * 4;

    float v0, v1, v2, v3;
    if (tkn < NC_) {
        const float4 s4 = *(const float4*)(slots + ((size_t)b*NC_ + tkn)*D_ + d0);
        const float4 p4 = *(const float4*)(spe + (size_t)tkn*D_ + d0);
        v0 = s4.x + p4.x; v1 = s4.y + p4.y; v2 = s4.z + p4.z; v3 = s4.w + p4.w;
    } else {
        const int p = tkn - NC_;
        const float4 p4 = *(const float4*)(pe + (size_t)p*D_ + d0);
        v0 = z[((size_t)b*D_ + d0 + 0)*256 + p] + p4.x;
        v1 = z[((size_t)b*D_ + d0 + 1)*256 + p] + p4.y;
        v2 = z[((size_t)b*D_ + d0 + 2)*256 + p] + p4.z;
        v3 = z[((size_t)b*D_ + d0 + 3)*256 + p] + p4.w;
    }
    float mean = blocksum128(v0+v1+v2+v3, red) * (1.f/512.f);
    float dx = v0-mean, dy = v1-mean, dz = v2-mean, dw = v3-mean;
    float var = blocksum128(dx*dx+dy*dy+dz*dz+dw*dw, red) * (1.f/512.f);
    float rs = rsqrtf(var + 1e-5f);
    const float4 wv = *(const float4*)(nw + d0);
    const float4 bv = *(const float4*)(nb + d0);
    float4 o;
    o.x = dx*rs*wv.x + bv.x;
    o.y = dy*rs*wv.y + bv.y;
    o.z = dz*rs*wv.z + bv.z;
    o.w = dw*rs*wv.w + bv.w;
    *(float4*)(x + (size_t)row*D_ + d0) = o;
}

// ---------------- layernorm ---------------------------------------------------
__global__ __launch_bounds__(128) void ln_kernel(
    const float* __restrict__ xin, const float* __restrict__ w,
    const float* __restrict__ bia, float* __restrict__ yout)
{
    __shared__ float red[4];
    const size_t row = blockIdx.x;
    const int t = threadIdx.x;
    const int d0 = t * 4;
    float4 v = *(const float4*)(xin + row*D_ + d0);
    float mean = blocksum128(v.x+v.y+v.z+v.w, red) * (1.f/512.f);
    float dx = v.x-mean, dy = v.y-mean, dz = v.z-mean, dw = v.w-mean;
    float var = blocksum128(dx*dx+dy*dy+dz*dz+dw*dw, red) * (1.f/512.f);
    float rs = rsqrtf(var + 1e-5f);
    const float4 wv = *(const float4*)(w + d0);
    const float4 bv = *(const float4*)(bia + d0);
    float4 o;
    o.x = dx*rs*wv.x + bv.x;
    o.y = dy*rs*wv.y + bv.y;
    o.z = dz*rs*wv.z + bv.z;
    o.w = dw*rs*wv.w + bv.w;
    *(float4*)(yout + row*D_ + d0) = o;
}

// ---------------- tf32 tensor-core GEMM (4-stage cp.async) --------------------
// C[M,N] = A[M,K] @ B[K,N] row-major. 128x128 tile, BK=16, 256 threads.
// EPI: 0 = store, 1 = C += acc + bias, 2 = C = gelu(acc + bias)
#define GA_STRIDE 20
#define GB_STRIDE 136
#define GA_SZ (128*GA_STRIDE)
#define GB_SZ (16*GB_STRIDE)
#define GEMM_STAGES 4
#define GEMM_SMEM_BYTES (GEMM_STAGES*(GA_SZ+GB_SZ)*4)

template<int EPI>
__global__ __launch_bounds__(256) void gemm_tf32(
    const float* __restrict__ A, const float* __restrict__ Bw,
    const float* __restrict__ bias, float* __restrict__ C,
    int M, int N, int K)
{
    extern __shared__ float sm[];
    float* AsBase = sm;
    float* BsBase = sm + GEMM_STAGES*GA_SZ;

    const int bm = blockIdx.y * 128;
    const int bn = blockIdx.x * 128;
    const int tid = threadIdx.x;
    const int warp = tid >> 5, lane = tid & 31;
    const int g = lane >> 2, tg = lane & 3;
    const int wm = (warp & 1) << 6;
    const int wn = (warp >> 1) << 5;

    float c[4][4][4];
    #pragma unroll
    for (int i=0;i<4;i++)
        #pragma unroll
        for (int j=0;j<4;j++)
            #pragma unroll
            for (int r=0;r<4;r++) c[i][j][r] = 0.f;

    const int ar0 = tid >> 2,  ar1 = (tid >> 2) + 64;
    const int acl = (tid & 3) * 4;
    const int br0 = tid >> 5,  br1 = (tid >> 5) + 8;
    const int bcl = (tid & 31) * 4;

    auto prefetch = [&](int kt, int st){
        float* As = AsBase + st*GA_SZ;
        float* Bs = BsBase + st*GB_SZ;
        cp16(As + ar0*GA_STRIDE + acl, A + (size_t)(bm+ar0)*K + kt*16 + acl);
        cp16(As + ar1*GA_STRIDE + acl, A + (size_t)(bm+ar1)*K + kt*16 + acl);
        cp16(Bs + br0*GB_STRIDE + bcl, Bw + (size_t)(kt*16+br0)*N + bn + bcl);
        cp16(Bs + br1*GB_STRIDE + bcl, Bw + (size_t)(kt*16+br1)*N + bn + bcl);
    };

    const int KT = K >> 4;
    prefetch(0,0); asm volatile("cp.async.commit_group;\n");
    prefetch(1,1); asm volatile("cp.async.commit_group;\n");
    prefetch(2,2); asm volatile("cp.async.commit_group;\n");

    for (int kt = 0; kt < KT; kt++){
        asm volatile("cp.async.wait_group 2;\n");
        __syncthreads();
        if (kt+3 < KT) prefetch(kt+3, (kt+3)&3);
        asm volatile("cp.async.commit_group;\n");

        const float* As = AsBase + (kt&3)*GA_SZ;
        const float* Bs = BsBase + (kt&3)*GB_SZ;
        #pragma unroll
        for (int ks=0; ks<2; ks++){
            const int kb = ks*8;
            uint32_t af[4][4], bf[4][2];
            #pragma unroll
            for (int mf=0; mf<4; mf++){
                int r0 = wm + mf*16 + g;
                af[mf][0] = __float_as_uint(As[ r0   *GA_STRIDE + kb + tg    ]);
                af[mf][1] = __float_as_uint(As[(r0+8)*GA_STRIDE + kb + tg    ]);
                af[mf][2] = __float_as_uint(As[ r0   *GA_STRIDE + kb + tg + 4]);
                af[mf][3] = __float_as_uint(As[(r0+8)*GA_STRIDE + kb + tg + 4]);
            }
            #pragma unroll
            for (int nf=0; nf<4; nf++){
                int cn = wn + nf*8 + g;
                bf[nf][0] = __float_as_uint(Bs[(kb+tg  )*GB_STRIDE + cn]);
                bf[nf][1] = __float_as_uint(Bs[(kb+tg+4)*GB_STRIDE + cn]);
            }
            #pragma unroll
            for (int mf=0; mf<4; mf++)
                #pragma unroll
                for (int nf=0; nf<4; nf++)
                    mma_tf32(c[mf][nf], af[mf], bf[nf][0], bf[nf][1]);
        }
    }

    // epilogue
    #pragma unroll
    for (int mf=0; mf<4; mf++){
        #pragma unroll
        for (int nf=0; nf<4; nf++){
            const int row = bm + wm + mf*16 + g;
            const int col = bn + wn + nf*8 + tg*2;
            #pragma unroll
            for (int half=0; half<2; half++){
                const int r = row + half*8;
                float v0 = c[mf][nf][half*2+0];
                float v1 = c[mf][nf][half*2+1];
                float* p = C + (size_t)r*N + col;
                if (EPI == 0){
                    p[0] = v0; p[1] = v1;
                } else if (EPI == 1){
                    p[0] += v0 + bias[col];
                    p[1] += v1 + bias[col+1];
                } else {
                    float t0 = v0 + bias[col];
                    float t1 = v1 + bias[col+1];
                    p[0] = 0.5f*t0*(1.f + erff(t0*0.70710678118654752f));
                    p[1] = 0.5f*t1*(1.f + erff(t1*0.70710678118654752f));
                }
            }
        }
    }
}

// ---------------- tensor-core causal flash attention --------------------------
// grid (S/64, NH, B), 128 threads (4 warps), 64-query tile, DH=64.
// S = Q K^T via mma tf32; online softmax in C-frag layout; P staged through
// per-warp smem (aliased onto Ks) to A-frag layout; O += P V via mma tf32.
#define KS_STRIDE 68
#define VS_STRIDE 72

__global__ __launch_bounds__(128) void attn_kernel(
    const float* __restrict__ qkv, float* __restrict__ o)
{
    __shared__ float Ks[64*KS_STRIDE];   // K tile; aliased as P region per warp
    __shared__ float Vs[64*VS_STRIDE];   // V tile; Q staging at start

    const int qt = blockIdx.x;
    const int h  = blockIdx.y;
    const int b  = blockIdx.z;
    const int tid = threadIdx.x;
    const int w = tid >> 5, lane = tid & 31;
    const int g = lane >> 2, tg = lane & 3;
    const int wr = w * 16;
    const size_t base = (size_t)b * S_ * 1536;
    const int q0 = qt * 64;

    // ---- stage Q (scaled, tf32) into Vs, pull fragments to registers ----
    #pragma unroll
    for (int i=0;i<8;i++){
        int lin = tid + 128*i;
        int r = lin >> 4, c4 = (lin & 15) * 4;
        float4 v = *(const float4*)(qkv + base + (size_t)(q0+r)*1536 + h*64 + c4);
        v.x = f2tf32(v.x*0.125f); v.y = f2tf32(v.y*0.125f);
        v.z = f2tf32(v.z*0.125f); v.w = f2tf32(v.w*0.125f);
        *(float4*)(Vs + r*VS_STRIDE + c4) = v;
    }
    __syncthreads();
    uint32_t aq[8][4];
    #pragma unroll
    for (int k=0;k<8;k++){
        aq[k][0] = __float_as_uint(Vs[(wr+g  )*VS_STRIDE + 8*k + tg    ]);
        aq[k][1] = __float_as_uint(Vs[(wr+g+8)*VS_STRIDE + 8*k + tg    ]);
        aq[k][2] = __float_as_uint(Vs[(wr+g  )*VS_STRIDE + 8*k + tg + 4]);
        aq[k][3] = __float_as_uint(Vs[(wr+g+8)*VS_STRIDE + 8*k + tg + 4]);
    }

    float oacc[8][4];
    #pragma unroll
    for (int nf=0;nf<8;nf++)
        #pragma unroll
        for (int r=0;r<4;r++) oacc[nf][r] = 0.f;
    float mrow[2] = {-1e30f, -1e30f};
    float lrow[2] = {0.f, 0.f};

    for (int jt = 0; jt <= qt; jt++){
        __syncthreads();   // prior-iteration Ps/Vs reads complete
        const int j0 = jt * 64;
        #pragma unroll
        for (int i=0;i<8;i++){
            int lin = tid + 128*i;
            int r = lin >> 4, c4 = (lin & 15) * 4;
            const float* kp = qkv + base + (size_t)(j0+r)*1536 + 512 + h*64 + c4;
            float4 kv = *(const float4*)kp;
            kv.x = f2tf32(kv.x); kv.y = f2tf32(kv.y);
            kv.z = f2tf32(kv.z); kv.w = f2tf32(kv.w);
            *(float4*)(Ks + r*KS_STRIDE + c4) = kv;
            float4 vv = *(const float4*)(kp + 512);
            vv.x = f2tf32(vv.x); vv.y = f2tf32(vv.y);
            vv.z = f2tf32(vv.z); vv.w = f2tf32(vv.w);
            *(float4*)(Vs + r*VS_STRIDE + c4) = vv;
        }
        __syncthreads();

        // ---- S = Q K^T ----
        float s[8][4];
        #pragma unroll
        for (int nf=0;nf<8;nf++)
            #pragma unroll
            for (int r=0;r<4;r++) s[nf][r] = 0.f;
        #pragma unroll
        for (int k=0;k<8;k++){
            #pragma unroll
            for (int nf=0;nf<8;nf++){
                uint32_t b0 = __float_as_uint(Ks[(nf*8+g)*KS_STRIDE + 8*k + tg    ]);
                uint32_t b1 = __float_as_uint(Ks[(nf*8+g)*KS_STRIDE + 8*k + tg + 4]);
                mma_tf32(s[nf], aq[k], b0, b1);
            }
        }

        // ---- causal mask on the diagonal tile ----
        if (jt == qt){
            const int r0 = wr + g, r1 = wr + g + 8;
            #pragma unroll
            for (int nf=0;nf<8;nf++){
                int c = nf*8 + tg*2;
                if (c   > r0) s[nf][0] = -1e30f;
                if (c+1 > r0) s[nf][1] = -1e30f;
                if (c   > r1) s[nf][2] = -1e30f;
                if (c+1 > r1) s[nf][3] = -1e30f;
            }
        }

        // ---- online softmax ----
        float mx0 = -1e30f, mx1 = -1e30f;
        #pragma unroll
        for (int nf=0;nf<8;nf++){
            mx0 = fmaxf(mx0, fmaxf(s[nf][0], s[nf][1]));
            mx1 = fmaxf(mx1, fmaxf(s[nf][2], s[nf][3]));
        }
        mx0 = fmaxf(mx0, __shfl_xor_sync(0xffffffffu, mx0, 1));
        mx0 = fmaxf(mx0, __shfl_xor_sync(0xffffffffu, mx0, 2));
        mx1 = fmaxf(mx1, __shfl_xor_sync(0xffffffffu, mx1, 1));
        mx1 = fmaxf(mx1, __shfl_xor_sync(0xffffffffu, mx1, 2));
        float nm0 = fmaxf(mrow[0], mx0), nm1 = fmaxf(mrow[1], mx1);
        float cr0 = __expf(mrow[0] - nm0), cr1 = __expf(mrow[1] - nm1);
        float sum0 = 0.f, sum1 = 0.f;
        #pragma unroll
        for (int nf=0;nf<8;nf++){
            s[nf][0] = __expf(s[nf][0] - nm0);
            s[nf][1] = __expf(s[nf][1] - nm0);
            s[nf][2] = __expf(s[nf][2] - nm1);
            s[nf][3] = __expf(s[nf][3] - nm1);
            sum0 += s[nf][0] + s[nf][1];
            sum1 += s[nf][2] + s[nf][3];
        }
        sum0 += __shfl_xor_sync(0xffffffffu, sum0, 1);
        sum0 += __shfl_xor_sync(0xffffffffu, sum0, 2);
        sum1 += __shfl_xor_sync(0xffffffffu, sum1, 1);
        sum1 += __shfl_xor_sync(0xffffffffu, sum1, 2);
        lrow[0] = lrow[0]*cr0 + sum0;
        lrow[1] = lrow[1]*cr1 + sum1;
        mrow[0] = nm0; mrow[1] = nm1;
        #pragma unroll
        for (int nf=0;nf<8;nf++){
            oacc[nf][0] *= cr0; oacc[nf][1] *= cr0;
            oacc[nf][2] *= cr1; oacc[nf][3] *= cr1;
        }

        __syncthreads();   // all warps done reading Ks for QK
        // ---- store P (tf32) into this warp's region of Ks ----
        float* Ps = Ks + wr*KS_STRIDE;
        #pragma unroll
        for (int nf=0;nf<8;nf++){
            int c = nf*8 + tg*2;
            *(float2*)(Ps + g*KS_STRIDE + c) =
                make_float2(f2tf32(s[nf][0]), f2tf32(s[nf][1]));
            *(float2*)(Ps + (g+8)*KS_STRIDE + c) =
                make_float2(f2tf32(s[nf][2]), f2tf32(s[nf][3]));
        }
        __syncwarp();

        // ---- O += P V ----
        #pragma unroll
        for (int k=0;k<8;k++){
            uint32_t ap[4];
            ap[0] = __float_as_uint(Ps[ g   *KS_STRIDE + 8*k + tg    ]);
            ap[1] = __float_as_uint(Ps[(g+8)*KS_STRIDE + 8*k + tg    ]);
            ap[2] = __float_as_uint(Ps[ g   *KS_STRIDE + 8*k + tg + 4]);
            ap[3] = __float_as_uint(Ps[(g+8)*KS_STRIDE + 8*k + tg + 4]);
            #pragma unroll
            for (int nf=0;nf<8;nf++){
                uint32_t b0 = __float_as_uint(Vs[(8*k+tg  )*VS_STRIDE + nf*8 + g]);
                uint32_t b1 = __float_as_uint(Vs[(8*k+tg+4)*VS_STRIDE + nf*8 + g]);
                mma_tf32(oacc[nf], ap, b0, b1);
            }
        }
    }

    // ---- write O ----
    const float inv0 = 1.f / lrow[0], inv1 = 1.f / lrow[1];
    const int row0 = q0 + wr + g, row1 = row0 + 8;
    #pragma unroll
    for (int nf=0;nf<8;nf++){
        int c = h*64 + nf*8 + tg*2;
        *(float2*)(o + (size_t)(b*S_ + row0)*D_ + c) =
            make_float2(oacc[nf][0]*inv0, oacc[nf][1]*inv0);
        *(float2*)(o + (size_t)(b*S_ + row1)*D_ + c) =
            make_float2(oacc[nf][2]*inv1, oacc[nf][3]*inv1);
    }
}

// ---------------- output slice + transpose -----------------------------------
__global__ __launch_bounds__(256) void out_kernel(
    const float* __restrict__ x, float* __restrict__ out)
{
    const int idx = blockIdx.x * 256 + threadIdx.x;
    const int p = idx & 255;
    const int d = (idx >> 8) & 511;
    const int b = idx >> 17;
    out[idx] = x[((size_t)b*S_ + (NC_ - 1) + p)*D_ + d];
}

// ---------------- launch ------------------------------------------------------
extern "C" void kernel_launch(void* const* d_in, const int* in_sizes, int n_in,
                              void* d_out, int out_size)
{
    const float* z       = (const float*)d_in[0];
    const float* slots   = (const float*)d_in[1];
    const float* pos_emb = (const float*)d_in[2];
    const float* spe     = (const float*)d_in[3];
    const float* norm_w  = (const float*)d_in[4];
    const float* norm_b  = (const float*)d_in[5];
    const float* ln1_w   = (const float*)d_in[6];
    const float* ln1_b   = (const float*)d_in[7];
    const float* qkv_w   = (const float*)d_in[8];
    const float* out_w   = (const float*)d_in[9];
    const float* out_b   = (const float*)d_in[10];
    const float* ln2_w   = (const float*)d_in[11];
    const float* ln2_b   = (const float*)d_in[12];
    const float* mlp_w1  = (const float*)d_in[13];
    const float* mlp_b1  = (const float*)d_in[14];
    const float* mlp_w2  = (const float*)d_in[15];
    const float* mlp_b2  = (const float*)d_in[16];

    float *x, *y, *big;
    cudaGetSymbolAddress((void**)&x,   g_x);
    cudaGetSymbolAddress((void**)&y,   g_y);
    cudaGetSymbolAddress((void**)&big, g_big);

    cudaFuncSetAttribute(gemm_tf32<0>, cudaFuncAttributeMaxDynamicSharedMemorySize, GEMM_SMEM_BYTES);
    cudaFuncSetAttribute(gemm_tf32<1>, cudaFuncAttributeMaxDynamicSharedMemorySize, GEMM_SMEM_BYTES);
    cudaFuncSetAttribute(gemm_tf32<2>, cudaFuncAttributeMaxDynamicSharedMemorySize, GEMM_SMEM_BYTES);

    embed_ln_kernel<<<M_, 128>>>(z, slots, pos_emb, spe, norm_w, norm_b, x);

    for (int i = 0; i < DEPTH_; i++){
        ln_kernel<<<M_, 128>>>(x, ln1_w + i*D_, ln1_b + i*D_, y);
        gemm_tf32<0><<<dim3(1536/128, M_/128), 256, GEMM_SMEM_BYTES>>>(
            y, qkv_w + (size_t)i*D_*1536, nullptr, big, M_, 1536, D_);
        attn_kernel<<<dim3(S_/64, NH_, B_), 128>>>(big, y);
        gemm_tf32<1><<<dim3(D_/128, M_/128), 256, GEMM_SMEM_BYTES>>>(
            y, out_w + (size_t)i*D_*D_, out_b + i*D_, x, M_, D_, D_);
        ln_kernel<<<M_, 128>>>(x, ln2_w + i*D_, ln2_b + i*D_, y);
        gemm_tf32<2><<<dim3(MLP_/128, M_/128), 256, GEMM_SMEM_BYTES>>>(
            y, mlp_w1 + (size_t)i*D_*MLP_, mlp_b1 + i*MLP_, big, M_, MLP_, D_);
        gemm_tf32<1><<<dim3(D_/128, M_/128), 256, GEMM_SMEM_BYTES>>>(
            big, mlp_w2 + (size_t)i*MLP_*D_, mlp_b2 + i*D_, x, M_, D_, MLP_);
    }

    out_kernel<<<(B_*D_*256)/256, 256>>>(x, (float*)d_out);
}

// round 4
// speedup vs baseline: 2.2630x; 1.5536x over previous
#include <cuda_runtime.h>
#include <cuda_fp16.h>
#include <cstdint>
#include <math.h>

// Problem constants
#define B_   32
#define D_   512
#define NH_  8
#define DH_  64
#define DEPTH_ 8
#define MLP_ 2048
#define NC_  256
#define S_   512
#define M_   (B_*S_)   // 16384 rows

// ---------------- scratch (device globals; no allocation allowed) -------------
__device__ __align__(256) float  g_x[M_*D_];          // residual stream (fp32)
__device__ __align__(256) __half g_yh[M_*D_];         // LN out / attn out (half)
__device__ __align__(256) __half g_bigh[M_*MLP_];     // qkv (stride 1536) / mlp hidden
__device__ __align__(256) __half g_wqkvT[DEPTH_*1536*D_];
__device__ __align__(256) __half g_woT  [DEPTH_*D_*D_];
__device__ __align__(256) __half g_w1T  [DEPTH_*MLP_*D_];
__device__ __align__(256) __half g_w2T  [DEPTH_*D_*MLP_];

// ---------------- helpers ----------------------------------------------------
__device__ __forceinline__ uint32_t smem_u32(const void* p){
    return (uint32_t)__cvta_generic_to_shared(p);
}
__device__ __forceinline__ void cp16(uint32_t s, const void* g){
    asm volatile("cp.async.cg.shared.global [%0], [%1], 16;\n" :: "r"(s), "l"(g));
}
__device__ __forceinline__ void mma_f16(float* c, const uint32_t* a,
                                        uint32_t b0, uint32_t b1){
    asm volatile(
        "mma.sync.aligned.m16n8k16.row.col.f32.f16.f16.f32 "
        "{%0,%1,%2,%3}, {%4,%5,%6,%7}, {%8,%9}, {%0,%1,%2,%3};"
        : "+f"(c[0]), "+f"(c[1]), "+f"(c[2]), "+f"(c[3])
        : "r"(a[0]), "r"(a[1]), "r"(a[2]), "r"(a[3]), "r"(b0), "r"(b1));
}
__device__ __forceinline__ void ldsm_x4_t(uint32_t& r0, uint32_t& r1,
                                          uint32_t& r2, uint32_t& r3, uint32_t a){
    asm volatile("ldmatrix.sync.aligned.m8n8.x4.trans.shared.b16 {%0,%1,%2,%3}, [%4];"
                 : "=r"(r0), "=r"(r1), "=r"(r2), "=r"(r3) : "r"(a));
}
__device__ __forceinline__ float blocksum128(float v, volatile float* red){
    #pragma unroll
    for (int o = 16; o > 0; o >>= 1) v += __shfl_xor_sync(0xffffffffu, v, o);
    if ((threadIdx.x & 31) == 0) red[threadIdx.x >> 5] = v;
    __syncthreads();
    float r = red[0] + red[1] + red[2] + red[3];
    __syncthreads();
    return r;
}

// ---------------- weight transpose (w[K,N] fp32 -> wt[N,K] half) --------------
__global__ __launch_bounds__(256) void transpose_w(
    const float* __restrict__ w, __half* __restrict__ wt, int K, int N)
{
    __shared__ float t[32][33];
    const float* wl = w + (size_t)blockIdx.z * K * N;
    __half* wtl = wt + (size_t)blockIdx.z * K * N;
    const int k0 = blockIdx.x*32, n0 = blockIdx.y*32;
    const int tx = threadIdx.x & 31, ty = threadIdx.x >> 5;
    #pragma unroll
    for (int i = ty; i < 32; i += 8)
        t[i][tx] = wl[(size_t)(k0+i)*N + n0 + tx];
    __syncthreads();
    #pragma unroll
    for (int i = ty; i < 32; i += 8)
        wtl[(size_t)(n0+i)*K + k0 + tx] = __float2half_rn(t[tx][i]);
}

// ---------------- embed + first LN (fp32 out) ---------------------------------
__global__ __launch_bounds__(128) void embed_ln_kernel(
    const float* __restrict__ z, const float* __restrict__ slots,
    const float* __restrict__ pe, const float* __restrict__ spe,
    const float* __restrict__ nw, const float* __restrict__ nb,
    float* __restrict__ x)
{
    __shared__ float red[4];
    const int row = blockIdx.x;
    const int b   = row >> 9;
    const int tkn = row & 511;
    const int t   = threadIdx.x;
    const int d0  = t * 4;

    float v0, v1, v2, v3;
    if (tkn < NC_) {
        const float4 s4 = *(const float4*)(slots + ((size_t)b*NC_ + tkn)*D_ + d0);
        const float4 p4 = *(const float4*)(spe + (size_t)tkn*D_ + d0);
        v0 = s4.x + p4.x; v1 = s4.y + p4.y; v2 = s4.z + p4.z; v3 = s4.w + p4.w;
    } else {
        const int p = tkn - NC_;
        const float4 p4 = *(const float4*)(pe + (size_t)p*D_ + d0);
        v0 = z[((size_t)b*D_ + d0 + 0)*256 + p] + p4.x;
        v1 = z[((size_t)b*D_ + d0 + 1)*256 + p] + p4.y;
        v2 = z[((size_t)b*D_ + d0 + 2)*256 + p] + p4.z;
        v3 = z[((size_t)b*D_ + d0 + 3)*256 + p] + p4.w;
    }
    float mean = blocksum128(v0+v1+v2+v3, red) * (1.f/512.f);
    float dx = v0-mean, dy = v1-mean, dz = v2-mean, dw = v3-mean;
    float var = blocksum128(dx*dx+dy*dy+dz*dz+dw*dw, red) * (1.f/512.f);
    float rs = rsqrtf(var + 1e-5f);
    const float4 wv = *(const float4*)(nw + d0);
    const float4 bv = *(const float4*)(nb + d0);
    float4 o;
    o.x = dx*rs*wv.x + bv.x;
    o.y = dy*rs*wv.y + bv.y;
    o.z = dz*rs*wv.z + bv.z;
    o.w = dw*rs*wv.w + bv.w;
    *(float4*)(x + (size_t)row*D_ + d0) = o;
}

// ---------------- layernorm (fp32 in -> half out) -----------------------------
__global__ __launch_bounds__(128) void ln_kernel(
    const float* __restrict__ xin, const float* __restrict__ w,
    const float* __restrict__ bia, __half* __restrict__ yout)
{
    __shared__ float red[4];
    const size_t row = blockIdx.x;
    const int t = threadIdx.x;
    const int d0 = t * 4;
    float4 v = *(const float4*)(xin + row*D_ + d0);
    float mean = blocksum128(v.x+v.y+v.z+v.w, red) * (1.f/512.f);
    float dx = v.x-mean, dy = v.y-mean, dz = v.z-mean, dw = v.w-mean;
    float var = blocksum128(dx*dx+dy*dy+dz*dz+dw*dw, red) * (1.f/512.f);
    float rs = rsqrtf(var + 1e-5f);
    const float4 wv = *(const float4*)(w + d0);
    const float4 bv = *(const float4*)(bia + d0);
    __half2 h0 = __floats2half2_rn(dx*rs*wv.x + bv.x, dy*rs*wv.y + bv.y);
    __half2 h1 = __floats2half2_rn(dz*rs*wv.z + bv.z, dw*rs*wv.w + bv.w);
    uint2 pk; pk.x = *(uint32_t*)&h0; pk.y = *(uint32_t*)&h1;
    *(uint2*)(yout + row*D_ + d0) = pk;
}

// ---------------- fp16 tensor-core GEMM (4-stage cp.async) --------------------
// C[M,N] = A[M,K] @ BT[N,K]^T, A/BT half. 128x128 tile, BK=32, 256 threads.
// EPI: 0 = store half, 1 = fp32 C += acc + bias, 2 = half C = gelu(acc + bias)
#define AS_STRIDE 40
#define AS_SZ (128*AS_STRIDE)     // halves
#define STAGE_HALVES (2*AS_SZ)
#define GEMM_SMEM_BYTES (4*STAGE_HALVES*2)

template<int EPI>
__global__ __launch_bounds__(256) void gemm_f16(
    const __half* __restrict__ A, const __half* __restrict__ BT,
    const float* __restrict__ bias, void* __restrict__ Cv,
    int M, int N, int K)
{
    extern __shared__ __half sm[];
    const int bm = blockIdx.y * 128;
    const int bn = blockIdx.x * 128;
    const int tid = threadIdx.x;
    const int warp = tid >> 5, lane = tid & 31;
    const int g = lane >> 2, tg = lane & 3;
    const int wm = (warp & 1) << 6;
    const int wn = (warp >> 1) << 5;

    float c[4][4][4];
    #pragma unroll
    for (int i=0;i<4;i++)
        #pragma unroll
        for (int j=0;j<4;j++)
            #pragma unroll
            for (int r=0;r<4;r++) c[i][j][r] = 0.f;

    const int lr = tid >> 1;             // 0..127
    const int lc = (tid & 1) * 16;       // 0 or 16

    auto prefetch = [&](int kt, int st){
        __half* As = sm + st*STAGE_HALVES;
        __half* Bs = As + AS_SZ;
        const __half* ga = A  + (size_t)(bm+lr)*K + kt*32 + lc;
        const __half* gb = BT + (size_t)(bn+lr)*K + kt*32 + lc;
        cp16(smem_u32(As + lr*AS_STRIDE + lc),     ga);
        cp16(smem_u32(As + lr*AS_STRIDE + lc + 8), ga + 8);
        cp16(smem_u32(Bs + lr*AS_STRIDE + lc),     gb);
        cp16(smem_u32(Bs + lr*AS_STRIDE + lc + 8), gb + 8);
    };

    const int KT = K >> 5;
    prefetch(0,0); asm volatile("cp.async.commit_group;\n");
    prefetch(1,1); asm volatile("cp.async.commit_group;\n");
    prefetch(2,2); asm volatile("cp.async.commit_group;\n");

    for (int kt = 0; kt < KT; kt++){
        asm volatile("cp.async.wait_group 2;\n");
        __syncthreads();
        if (kt+3 < KT) prefetch(kt+3, (kt+3)&3);
        asm volatile("cp.async.commit_group;\n");

        const __half* As = sm + (kt&3)*STAGE_HALVES;
        const __half* Bs = As + AS_SZ;
        #pragma unroll
        for (int ks=0; ks<2; ks++){
            const int kb = ks*16;
            uint32_t af[4][4], bf[4][2];
            #pragma unroll
            for (int mf=0; mf<4; mf++){
                int r0 = wm + mf*16 + g;
                af[mf][0] = *(const uint32_t*)&As[ r0   *AS_STRIDE + kb + 2*tg    ];
                af[mf][1] = *(const uint32_t*)&As[(r0+8)*AS_STRIDE + kb + 2*tg    ];
                af[mf][2] = *(const uint32_t*)&As[ r0   *AS_STRIDE + kb + 2*tg + 8];
                af[mf][3] = *(const uint32_t*)&As[(r0+8)*AS_STRIDE + kb + 2*tg + 8];
            }
            #pragma unroll
            for (int nf=0; nf<4; nf++){
                int n0 = wn + nf*8 + g;
                bf[nf][0] = *(const uint32_t*)&Bs[n0*AS_STRIDE + kb + 2*tg    ];
                bf[nf][1] = *(const uint32_t*)&Bs[n0*AS_STRIDE + kb + 2*tg + 8];
            }
            #pragma unroll
            for (int mf=0; mf<4; mf++)
                #pragma unroll
                for (int nf=0; nf<4; nf++)
                    mma_f16(c[mf][nf], af[mf], bf[nf][0], bf[nf][1]);
        }
    }

    // epilogue
    #pragma unroll
    for (int mf=0; mf<4; mf++){
        #pragma unroll
        for (int nf=0; nf<4; nf++){
            const int row = bm + wm + mf*16 + g;
            const int col = bn + wn + nf*8 + tg*2;
            #pragma unroll
            for (int half_=0; half_<2; half_++){
                const int r = row + half_*8;
                float v0 = c[mf][nf][half_*2+0];
                float v1 = c[mf][nf][half_*2+1];
                if (EPI == 0){
                    __half2 h = __floats2half2_rn(v0, v1);
                    *(uint32_t*)((__half*)Cv + (size_t)r*N + col) = *(uint32_t*)&h;
                } else if (EPI == 1){
                    float* p = (float*)Cv + (size_t)r*N + col;
                    p[0] += v0 + bias[col];
                    p[1] += v1 + bias[col+1];
                } else {
                    float t0 = v0 + bias[col];
                    float t1 = v1 + bias[col+1];
                    t0 = 0.5f*t0*(1.f + erff(t0*0.70710678118654752f));
                    t1 = 0.5f*t1*(1.f + erff(t1*0.70710678118654752f));
                    __half2 h = __floats2half2_rn(t0, t1);
                    *(uint32_t*)((__half*)Cv + (size_t)r*N + col) = *(uint32_t*)&h;
                }
            }
        }
    }
}

// ---------------- fp16 tensor-core causal flash attention ---------------------
// grid (S/64, NH, B), 128 threads (4 warps), 64-query tile, DH=64.
#define KS_STRIDE 72
#define VS_STRIDE 72

__global__ __launch_bounds__(128) void attn_kernel(
    const __half* __restrict__ qkv, __half* __restrict__ o)
{
    __shared__ __align__(16) __half Ks[64*KS_STRIDE];  // K tile; P region per warp
    __shared__ __align__(16) __half Vs[64*VS_STRIDE];  // V tile; Q staging at start

    const int qt = blockIdx.x;
    const int h  = blockIdx.y;
    const int b  = blockIdx.z;
    const int tid = threadIdx.x;
    const int w = tid >> 5, lane = tid & 31;
    const int g = lane >> 2, tg = lane & 3;
    const int wr = w * 16;
    const size_t base = (size_t)b * S_ * 1536;
    const int q0 = qt * 64;

    // ---- stage Q (scaled) into Vs, pull A-fragments ----
    {
        const __half2 sc = __floats2half2_rn(0.125f, 0.125f);
        #pragma unroll
        for (int i=0;i<4;i++){
            int lin = tid + 128*i;
            int r = lin >> 3, c8 = (lin & 7) * 8;
            uint4 v = *(const uint4*)(qkv + base + (size_t)(q0+r)*1536 + h*64 + c8);
            __half2* hp = (__half2*)&v;
            hp[0] = __hmul2(hp[0], sc); hp[1] = __hmul2(hp[1], sc);
            hp[2] = __hmul2(hp[2], sc); hp[3] = __hmul2(hp[3], sc);
            *(uint4*)(Vs + r*VS_STRIDE + c8) = v;
        }
    }
    __syncthreads();
    uint32_t aq[4][4];
    #pragma unroll
    for (int kg=0;kg<4;kg++){
        aq[kg][0] = *(const uint32_t*)&Vs[(wr+g  )*VS_STRIDE + 16*kg + 2*tg    ];
        aq[kg][1] = *(const uint32_t*)&Vs[(wr+g+8)*VS_STRIDE + 16*kg + 2*tg    ];
        aq[kg][2] = *(const uint32_t*)&Vs[(wr+g  )*VS_STRIDE + 16*kg + 2*tg + 8];
        aq[kg][3] = *(const uint32_t*)&Vs[(wr+g+8)*VS_STRIDE + 16*kg + 2*tg + 8];
    }

    float oacc[8][4];
    #pragma unroll
    for (int nf=0;nf<8;nf++)
        #pragma unroll
        for (int r=0;r<4;r++) oacc[nf][r] = 0.f;
    float mrow[2] = {-1e30f, -1e30f};
    float lrow[2] = {0.f, 0.f};

    for (int jt = 0; jt <= qt; jt++){
        __syncthreads();   // prior-iteration Ks/Vs reads complete
        const int j0 = jt * 64;
        #pragma unroll
        for (int i=0;i<4;i++){
            int lin = tid + 128*i;
            int r = lin >> 3, c8 = (lin & 7) * 8;
            const __half* kp = qkv + base + (size_t)(j0+r)*1536 + 512 + h*64 + c8;
            *(uint4*)(Ks + r*KS_STRIDE + c8) = *(const uint4*)kp;
            *(uint4*)(Vs + r*VS_STRIDE + c8) = *(const uint4*)(kp + 512);
        }
        __syncthreads();

        // ---- S = Q K^T ----
        float s[8][4];
        #pragma unroll
        for (int nf=0;nf<8;nf++)
            #pragma unroll
            for (int r=0;r<4;r++) s[nf][r] = 0.f;
        #pragma unroll
        for (int kg=0;kg<4;kg++){
            #pragma unroll
            for (int nf=0;nf<8;nf++){
                uint32_t b0 = *(const uint32_t*)&Ks[(nf*8+g)*KS_STRIDE + 16*kg + 2*tg    ];
                uint32_t b1 = *(const uint32_t*)&Ks[(nf*8+g)*KS_STRIDE + 16*kg + 2*tg + 8];
                mma_f16(s[nf], aq[kg], b0, b1);
            }
        }

        // ---- causal mask on the diagonal tile ----
        if (jt == qt){
            const int r0 = wr + g, r1 = wr + g + 8;
            #pragma unroll
            for (int nf=0;nf<8;nf++){
                int c = nf*8 + tg*2;
                if (c   > r0) s[nf][0] = -1e30f;
                if (c+1 > r0) s[nf][1] = -1e30f;
                if (c   > r1) s[nf][2] = -1e30f;
                if (c+1 > r1) s[nf][3] = -1e30f;
            }
        }

        // ---- online softmax ----
        float mx0 = -1e30f, mx1 = -1e30f;
        #pragma unroll
        for (int nf=0;nf<8;nf++){
            mx0 = fmaxf(mx0, fmaxf(s[nf][0], s[nf][1]));
            mx1 = fmaxf(mx1, fmaxf(s[nf][2], s[nf][3]));
        }
        mx0 = fmaxf(mx0, __shfl_xor_sync(0xffffffffu, mx0, 1));
        mx0 = fmaxf(mx0, __shfl_xor_sync(0xffffffffu, mx0, 2));
        mx1 = fmaxf(mx1, __shfl_xor_sync(0xffffffffu, mx1, 1));
        mx1 = fmaxf(mx1, __shfl_xor_sync(0xffffffffu, mx1, 2));
        float nm0 = fmaxf(mrow[0], mx0), nm1 = fmaxf(mrow[1], mx1);
        float cr0 = __expf(mrow[0] - nm0), cr1 = __expf(mrow[1] - nm1);
        float sum0 = 0.f, sum1 = 0.f;
        #pragma unroll
        for (int nf=0;nf<8;nf++){
            s[nf][0] = __expf(s[nf][0] - nm0);
            s[nf][1] = __expf(s[nf][1] - nm0);
            s[nf][2] = __expf(s[nf][2] - nm1);
            s[nf][3] = __expf(s[nf][3] - nm1);
            sum0 += s[nf][0] + s[nf][1];
            sum1 += s[nf][2] + s[nf][3];
        }
        sum0 += __shfl_xor_sync(0xffffffffu, sum0, 1);
        sum0 += __shfl_xor_sync(0xffffffffu, sum0, 2);
        sum1 += __shfl_xor_sync(0xffffffffu, sum1, 1);
        sum1 += __shfl_xor_sync(0xffffffffu, sum1, 2);
        lrow[0] = lrow[0]*cr0 + sum0;
        lrow[1] = lrow[1]*cr1 + sum1;
        mrow[0] = nm0; mrow[1] = nm1;
        #pragma unroll
        for (int nf=0;nf<8;nf++){
            oacc[nf][0] *= cr0; oacc[nf][1] *= cr0;
            oacc[nf][2] *= cr1; oacc[nf][3] *= cr1;
        }

        __syncthreads();   // all warps done reading Ks
        // ---- store P (half) into this warp's Ks slice ----
        __half* Ps = Ks + wr*KS_STRIDE;
        #pragma unroll
        for (int nf=0;nf<8;nf++){
            int c = nf*8 + tg*2;
            __half2 p0 = __floats2half2_rn(s[nf][0], s[nf][1]);
            __half2 p1 = __floats2half2_rn(s[nf][2], s[nf][3]);
            *(uint32_t*)(Ps +  g   *KS_STRIDE + c) = *(uint32_t*)&p0;
            *(uint32_t*)(Ps + (g+8)*KS_STRIDE + c) = *(uint32_t*)&p1;
        }
        __syncwarp();

        // ---- O += P V ----
        #pragma unroll
        for (int kg=0;kg<4;kg++){
            uint32_t ap[4];
            ap[0] = *(const uint32_t*)&Ps[ g   *KS_STRIDE + 16*kg + 2*tg    ];
            ap[1] = *(const uint32_t*)&Ps[(g+8)*KS_STRIDE + 16*kg + 2*tg    ];
            ap[2] = *(const uint32_t*)&Ps[ g   *KS_STRIDE + 16*kg + 2*tg + 8];
            ap[3] = *(const uint32_t*)&Ps[(g+8)*KS_STRIDE + 16*kg + 2*tg + 8];
            #pragma unroll
            for (int nh=0;nh<4;nh++){
                // ldmatrix.x4.trans: V[kg*16 + lane%16][nh*16 + (lane/16)*8]
                uint32_t addr = smem_u32(
                    Vs + (kg*16 + (lane & 15))*VS_STRIDE + nh*16 + (lane >> 4)*8);
                uint32_t b0,b1,b2,b3;
                ldsm_x4_t(b0,b1,b2,b3, addr);
                mma_f16(oacc[2*nh  ], ap, b0, b1);
                mma_f16(oacc[2*nh+1], ap, b2, b3);
            }
        }
    }

    // ---- write O (half) ----
    const float inv0 = 1.f / lrow[0], inv1 = 1.f / lrow[1];
    const int row0 = q0 + wr + g, row1 = row0 + 8;
    #pragma unroll
    for (int nf=0;nf<8;nf++){
        int c = h*64 + nf*8 + tg*2;
        __half2 h0 = __floats2half2_rn(oacc[nf][0]*inv0, oacc[nf][1]*inv0);
        __half2 h1 = __floats2half2_rn(oacc[nf][2]*inv1, oacc[nf][3]*inv1);
        *(uint32_t*)(o + (size_t)(b*S_ + row0)*D_ + c) = *(uint32_t*)&h0;
        *(uint32_t*)(o + (size_t)(b*S_ + row1)*D_ + c) = *(uint32_t*)&h1;
    }
}

// ---------------- output slice + transpose -----------------------------------
__global__ __launch_bounds__(256) void out_kernel(
    const float* __restrict__ x, float* __restrict__ out)
{
    const int idx = blockIdx.x * 256 + threadIdx.x;
    const int p = idx & 255;
    const int d = (idx >> 8) & 511;
    const int b = idx >> 17;
    out[idx] = x[((size_t)b*S_ + (NC_ - 1) + p)*D_ + d];
}

// ---------------- launch ------------------------------------------------------
extern "C" void kernel_launch(void* const* d_in, const int* in_sizes, int n_in,
                              void* d_out, int out_size)
{
    const float* z       = (const float*)d_in[0];
    const float* slots   = (const float*)d_in[1];
    const float* pos_emb = (const float*)d_in[2];
    const float* spe     = (const float*)d_in[3];
    const float* norm_w  = (const float*)d_in[4];
    const float* norm_b  = (const float*)d_in[5];
    const float* ln1_w   = (const float*)d_in[6];
    const float* ln1_b   = (const float*)d_in[7];
    const float* qkv_w   = (const float*)d_in[8];
    const float* out_w   = (const float*)d_in[9];
    const float* out_b   = (const float*)d_in[10];
    const float* ln2_w   = (const float*)d_in[11];
    const float* ln2_b   = (const float*)d_in[12];
    const float* mlp_w1  = (const float*)d_in[13];
    const float* mlp_b1  = (const float*)d_in[14];
    const float* mlp_w2  = (const float*)d_in[15];
    const float* mlp_b2  = (const float*)d_in[16];

    float *x;  __half *yh, *bigh, *wq, *wo, *w1, *w2;
    cudaGetSymbolAddress((void**)&x,    g_x);
    cudaGetSymbolAddress((void**)&yh,   g_yh);
    cudaGetSymbolAddress((void**)&bigh, g_bigh);
    cudaGetSymbolAddress((void**)&wq,   g_wqkvT);
    cudaGetSymbolAddress((void**)&wo,   g_woT);
    cudaGetSymbolAddress((void**)&w1,   g_w1T);
    cudaGetSymbolAddress((void**)&w2,   g_w2T);

    cudaFuncSetAttribute(gemm_f16<0>, cudaFuncAttributeMaxDynamicSharedMemorySize, GEMM_SMEM_BYTES);
    cudaFuncSetAttribute(gemm_f16<1>, cudaFuncAttributeMaxDynamicSharedMemorySize, GEMM_SMEM_BYTES);
    cudaFuncSetAttribute(gemm_f16<2>, cudaFuncAttributeMaxDynamicSharedMemorySize, GEMM_SMEM_BYTES);

    // transpose + convert weights to [N,K] half
    transpose_w<<<dim3(16,48,8), 256>>>(qkv_w, wq, 512, 1536);
    transpose_w<<<dim3(16,16,8), 256>>>(out_w, wo, 512, 512);
    transpose_w<<<dim3(16,64,8), 256>>>(mlp_w1, w1, 512, 2048);
    transpose_w<<<dim3(64,16,8), 256>>>(mlp_w2, w2, 2048, 512);

    embed_ln_kernel<<<M_, 128>>>(z, slots, pos_emb, spe, norm_w, norm_b, x);

    for (int i = 0; i < DEPTH_; i++){
        ln_kernel<<<M_, 128>>>(x, ln1_w + i*D_, ln1_b + i*D_, yh);
        gemm_f16<0><<<dim3(12, 128), 256, GEMM_SMEM_BYTES>>>(
            yh, wq + (size_t)i*1536*D_, nullptr, bigh, M_, 1536, D_);
        attn_kernel<<<dim3(S_/64, NH_, B_), 128>>>(bigh, yh);
        gemm_f16<1><<<dim3(4, 128), 256, GEMM_SMEM_BYTES>>>(
            yh, wo + (size_t)i*D_*D_, out_b + i*D_, x, M_, D_, D_);
        ln_kernel<<<M_, 128>>>(x, ln2_w + i*D_, ln2_b + i*D_, yh);
        gemm_f16<2><<<dim3(16, 128), 256, GEMM_SMEM_BYTES>>>(
            yh, w1 + (size_t)i*MLP_*D_, mlp_b1 + i*MLP_, bigh, M_, MLP_, D_);
        gemm_f16<1><<<dim3(4, 128), 256, GEMM_SMEM_BYTES>>>(
            bigh, w2 + (size_t)i*D_*MLP_, mlp_b2 + i*D_, x, M_, D_, MLP_);
    }

    out_kernel<<<(B_*D_*256)/256, 256>>>(x, (float*)d_out);
}